// round 14
// baseline (speedup 1.0000x reference)
#include <cuda_runtime.h>
#include <math.h>

#define N_NODES 50000
#define N_EDGES 800000
#define FEAT    128
#define SCAN_BLOCKS 196   // ceil(50000/256)

// Scratch (device globals; no allocation allowed in kernel_launch).
__device__ float g_w[N_NODES];                 // w = exp(x @ a)
__device__ int   g_cnt[N_NODES];               // degree (re-zeroed by scanA)
__device__ int   g_rowptr[N_NODES + 1];        // CSR row pointers (global)
__device__ int   g_blocksum[SCAN_BLOCKS];      // scan partials
__device__ __align__(16) int g_rank[N_EDGES];  // edge rank within its row
__device__ __align__(16) int g_cidx[N_EDGES];  // CSR column indices

// K1: fused — w[i] = exp(dot(x[i,:], a)) (warp per node),
// degree histogram + per-edge rank capture (thread per edge).
__global__ void k_score(const float* __restrict__ x, const float* __restrict__ a,
                        const int* __restrict__ row) {
    __shared__ float sa[FEAT];
    int tid = threadIdx.x;
    if (tid < FEAT) sa[tid] = a[tid];
    __syncthreads();
    int gt = blockIdx.x * blockDim.x + tid;

    // histogram + rank (the atomic's return value IS the rank)
    if (gt < N_EDGES) g_rank[gt] = atomicAdd(&g_cnt[row[gt]], 1);

    int gwarp = gt >> 5;
    int lane = tid & 31;
    if (gwarp >= N_NODES) return;
    float4 v = ((const float4*)x)[gwarp * 32 + lane];
    float4 w = ((const float4*)sa)[lane];
    float s = v.x * w.x + v.y * w.y + v.z * w.z + v.w * w.w;
    #pragma unroll
    for (int o = 16; o; o >>= 1) s += __shfl_xor_sync(0xffffffffu, s, o);
    if (lane == 0) g_w[gwarp] = expf(s);   // e ~ N(0, sqrt(2)) -> exp safe in fp32
}

// K2a: per-block exclusive scan of g_cnt -> g_rowptr (local), totals -> g_blocksum.
// Re-zeroes g_cnt for the next graph replay.
__global__ void k_scanA() {
    int i = blockIdx.x * 256 + threadIdx.x;
    int v = 0;
    if (i < N_NODES) { v = g_cnt[i]; g_cnt[i] = 0; }
    int lane = threadIdx.x & 31, w = threadIdx.x >> 5;
    int s = v;
    #pragma unroll
    for (int o = 1; o < 32; o <<= 1) {
        int t = __shfl_up_sync(0xffffffffu, s, o);
        if (lane >= o) s += t;
    }
    __shared__ int ws[8];
    if (lane == 31) ws[w] = s;
    __syncthreads();
    if (w == 0) {
        int t = (lane < 8) ? ws[lane] : 0;
        #pragma unroll
        for (int o = 1; o < 8; o <<= 1) {
            int u = __shfl_up_sync(0xffffffffu, t, o);
            if (lane >= o) t += u;
        }
        if (lane < 8) ws[lane] = t;
    }
    __syncthreads();
    int excl = s - v + (w > 0 ? ws[w - 1] : 0);
    if (i < N_NODES) g_rowptr[i] = excl;
    if (threadIdx.x == 0) g_blocksum[blockIdx.x] = ws[7];
}

// K2b: each block computes its prefix over g_blocksum by block-reduce,
// adds it to its rowptr slice.
__global__ void k_scanB() {
    int tid = threadIdx.x;
    int v = (tid < SCAN_BLOCKS && tid < blockIdx.x) ? g_blocksum[tid] : 0;
    int lane = tid & 31, w = tid >> 5;
    #pragma unroll
    for (int o = 16; o; o >>= 1) v += __shfl_xor_sync(0xffffffffu, v, o);
    __shared__ int ws[8];
    if (lane == 0) ws[w] = v;
    __syncthreads();
    if (tid == 0) {
        int t = 0;
        #pragma unroll
        for (int j = 0; j < 8; j++) t += ws[j];
        ws[0] = t;
    }
    __syncthreads();
    int prefix = ws[0];

    int i = blockIdx.x * 256 + tid;
    if (i < N_NODES) g_rowptr[i] += prefix;
    if (i == 0) g_rowptr[N_NODES] = N_EDGES;
}

// K3: counting-sort fill — NO atomics, NO w gather. Per edge: one rowptr
// gather + one 4B cidx scatter. 2 edges/thread.
__global__ void k_fill(const int* __restrict__ row, const int* __restrict__ col) {
    int t = blockIdx.x * blockDim.x + threadIdx.x;   // N_EDGES/2 threads
    if (t >= N_EDGES / 2) return;
    int2 r2 = ((const int2*)row)[t];
    int2 c2 = ((const int2*)col)[t];
    int2 k2 = ((const int2*)g_rank)[t];

    int p0 = g_rowptr[r2.x] + k2.x;
    int p1 = g_rowptr[r2.y] + k2.y;

    g_cidx[p0] = c2.x;
    g_cidx[p1] = c2.y;
}

// K4: warp per row, HALF-WARP per edge, fp32 features with packed f32x2 FMA.
// Per edge per lane: 2x ld.global.nc.v2.u64 (32B of the 512B row), weight
// broadcast packed once, 4x fma.rn.f32x2 (FFMA2). Accumulators are b64 pairs.
__global__ void k_row(const float* __restrict__ x, float* __restrict__ h) {
    int gw = (blockIdx.x * blockDim.x + threadIdx.x) >> 5;
    int lane = threadIdx.x & 31;
    if (gw >= N_NODES) return;
    int s0 = g_rowptr[gw], s1 = g_rowptr[gw + 1];

    int half = lane >> 4;        // 0 or 1
    int hl   = lane & 15;        // lane within half-warp: 32B slice of the row

    unsigned long long a0 = 0ull, a1 = 0ull, a2 = 0ull, a3 = 0ull;  // 8 fp32 accum
    float wsum = 0.0f;

    for (int i = s0 + half; i < s1; i += 2) {
        int c = __ldg(&g_cidx[i]);           // broadcast within half-warp
        float wgt = __ldg(&g_w[c]);          // broadcast gather (hot in L1/L2)
        wsum += wgt;
        unsigned long long ww;
        asm("mov.b64 %0, {%1, %1};" : "=l"(ww) : "f"(wgt));
        const float* p = x + (size_t)c * FEAT + hl * 8;
        unsigned long long v0, v1, v2, v3;
        asm("ld.global.nc.v2.u64 {%0, %1}, [%2];" : "=l"(v0), "=l"(v1) : "l"(p));
        asm("ld.global.nc.v2.u64 {%0, %1}, [%2];" : "=l"(v2), "=l"(v3) : "l"(p + 4));
        asm("fma.rn.f32x2 %0, %1, %2, %0;" : "+l"(a0) : "l"(ww), "l"(v0));
        asm("fma.rn.f32x2 %0, %1, %2, %0;" : "+l"(a1) : "l"(ww), "l"(v1));
        asm("fma.rn.f32x2 %0, %1, %2, %0;" : "+l"(a2) : "l"(ww), "l"(v2));
        asm("fma.rn.f32x2 %0, %1, %2, %0;" : "+l"(a3) : "l"(ww), "l"(v3));
    }

    // combine the two half-warps (lane i += lane i+16), f32x2 adds
    {
        unsigned long long b0 = __shfl_down_sync(0xffffffffu, a0, 16);
        unsigned long long b1 = __shfl_down_sync(0xffffffffu, a1, 16);
        unsigned long long b2 = __shfl_down_sync(0xffffffffu, a2, 16);
        unsigned long long b3 = __shfl_down_sync(0xffffffffu, a3, 16);
        asm("add.rn.f32x2 %0, %0, %1;" : "+l"(a0) : "l"(b0));
        asm("add.rn.f32x2 %0, %0, %1;" : "+l"(a1) : "l"(b1));
        asm("add.rn.f32x2 %0, %0, %1;" : "+l"(a2) : "l"(b2));
        asm("add.rn.f32x2 %0, %0, %1;" : "+l"(a3) : "l"(b3));
        wsum += __shfl_down_sync(0xffffffffu, wsum, 16);
    }

    if (half == 0) {
        float inv = (s1 > s0) ? 1.0f / wsum : 0.0f;
        float f[8];
        asm("mov.b64 {%0, %1}, %2;" : "=f"(f[0]), "=f"(f[1]) : "l"(a0));
        asm("mov.b64 {%0, %1}, %2;" : "=f"(f[2]), "=f"(f[3]) : "l"(a1));
        asm("mov.b64 {%0, %1}, %2;" : "=f"(f[4]), "=f"(f[5]) : "l"(a2));
        asm("mov.b64 {%0, %1}, %2;" : "=f"(f[6]), "=f"(f[7]) : "l"(a3));
        float4 o0 = make_float4(f[0] * inv, f[1] * inv, f[2] * inv, f[3] * inv);
        float4 o1 = make_float4(f[4] * inv, f[5] * inv, f[6] * inv, f[7] * inv);
        float4* dst = (float4*)(h + (size_t)gw * FEAT + hl * 8);
        dst[0] = o0;
        dst[1] = o1;
    }
}

extern "C" void kernel_launch(void* const* d_in, const int* in_sizes, int n_in,
                              void* d_out, int out_size) {
    const float* x   = (const float*)d_in[0];  // [N_NODES, FEAT]
    const float* a   = (const float*)d_in[1];  // [FEAT, 1]
    const int*   row = (const int*)d_in[2];    // [N_EDGES] int32
    const int*   col = (const int*)d_in[3];    // [N_EDGES] int32
    float* h = (float*)d_out;                  // [N_NODES, FEAT]

    int score_blocks = (N_NODES * 32 + 255) / 256;   // warp/node + thread/edge
    k_score<<<score_blocks, 256>>>(x, a, row);

    k_scanA<<<SCAN_BLOCKS, 256>>>();
    k_scanB<<<SCAN_BLOCKS, 256>>>();

    int fill_blocks = (N_EDGES / 2 + 255) / 256;     // 2 edges per thread
    k_fill<<<fill_blocks, 256>>>(row, col);

    int row_blocks = (N_NODES * 32 + 255) / 256;     // warp per row
    k_row<<<row_blocks, 256>>>(x, h);
}

// round 15
// speedup vs baseline: 1.1896x; 1.1896x over previous
#include <cuda_runtime.h>
#include <cuda_fp16.h>
#include <math.h>

#define N_NODES 50000
#define N_EDGES 800000
#define FEAT    128
#define SCAN_BLOCKS 196   // ceil(50000/256)

// Scratch (device globals; no allocation allowed in kernel_launch).
__device__ float g_w[N_NODES];                        // w = exp(x @ a)
__device__ int   g_cnt[N_NODES];                      // degree (re-zeroed by scanA)
__device__ int   g_rowptr[N_NODES + 1];               // CSR row pointers
__device__ int   g_blocksum[SCAN_BLOCKS];             // scan partials
__device__ __align__(16) int g_rank[N_EDGES];         // edge rank within its row
__device__ __align__(16) int g_cidx[N_EDGES];         // CSR column indices
__device__ __align__(16) __half g_xh[N_NODES * FEAT]; // fp16 copy of x

// K1: fused — w[i] = exp(dot(x[i,:], a)) (warp per node), fp16 copy of x,
// degree histogram + per-edge rank capture (thread per edge).
__global__ void k_score(const float* __restrict__ x, const float* __restrict__ a,
                        const int* __restrict__ row) {
    __shared__ float sa[FEAT];
    int tid = threadIdx.x;
    if (tid < FEAT) sa[tid] = a[tid];
    __syncthreads();
    int gt = blockIdx.x * blockDim.x + tid;

    // histogram + rank (the atomic's return value IS the rank)
    if (gt < N_EDGES) g_rank[gt] = atomicAdd(&g_cnt[row[gt]], 1);

    int gwarp = gt >> 5;
    int lane = tid & 31;
    if (gwarp >= N_NODES) return;
    float4 v = ((const float4*)x)[gwarp * 32 + lane];

    __half2 p0 = __floats2half2_rn(v.x, v.y);
    __half2 p1 = __floats2half2_rn(v.z, v.w);
    uint2 packed;
    packed.x = *(unsigned int*)&p0;
    packed.y = *(unsigned int*)&p1;
    ((uint2*)g_xh)[gwarp * 32 + lane] = packed;

    float4 w = ((const float4*)sa)[lane];
    float s = v.x * w.x + v.y * w.y + v.z * w.z + v.w * w.w;
    #pragma unroll
    for (int o = 16; o; o >>= 1) s += __shfl_xor_sync(0xffffffffu, s, o);
    if (lane == 0) g_w[gwarp] = expf(s);   // e ~ N(0, sqrt(2)) -> exp safe in fp32
}

// K2a: per-block exclusive scan of g_cnt -> g_rowptr (local), totals -> g_blocksum.
// Re-zeroes g_cnt for the next graph replay.
__global__ void k_scanA() {
    int i = blockIdx.x * 256 + threadIdx.x;
    int v = 0;
    if (i < N_NODES) { v = g_cnt[i]; g_cnt[i] = 0; }
    int lane = threadIdx.x & 31, w = threadIdx.x >> 5;
    int s = v;
    #pragma unroll
    for (int o = 1; o < 32; o <<= 1) {
        int t = __shfl_up_sync(0xffffffffu, s, o);
        if (lane >= o) s += t;
    }
    __shared__ int ws[8];
    if (lane == 31) ws[w] = s;
    __syncthreads();
    if (w == 0) {
        int t = (lane < 8) ? ws[lane] : 0;
        #pragma unroll
        for (int o = 1; o < 8; o <<= 1) {
            int u = __shfl_up_sync(0xffffffffu, t, o);
            if (lane >= o) t += u;
        }
        if (lane < 8) ws[lane] = t;
    }
    __syncthreads();
    int excl = s - v + (w > 0 ? ws[w - 1] : 0);
    if (i < N_NODES) g_rowptr[i] = excl;
    if (threadIdx.x == 0) g_blocksum[blockIdx.x] = ws[7];
}

// K2b: each block computes its prefix over g_blocksum by block-reduce,
// adds it to its rowptr slice.
__global__ void k_scanB() {
    int tid = threadIdx.x;
    int v = (tid < SCAN_BLOCKS && tid < blockIdx.x) ? g_blocksum[tid] : 0;
    int lane = tid & 31, w = tid >> 5;
    #pragma unroll
    for (int o = 16; o; o >>= 1) v += __shfl_xor_sync(0xffffffffu, v, o);
    __shared__ int ws[8];
    if (lane == 0) ws[w] = v;
    __syncthreads();
    if (tid == 0) {
        int t = 0;
        #pragma unroll
        for (int j = 0; j < 8; j++) t += ws[j];
        ws[0] = t;
    }
    __syncthreads();
    int prefix = ws[0];

    int i = blockIdx.x * 256 + tid;
    if (i < N_NODES) g_rowptr[i] += prefix;
    if (i == 0) g_rowptr[N_NODES] = N_EDGES;
}

// K3: counting-sort fill — NO atomics, NO w gather. Per edge: one rowptr
// gather + one 4B cidx scatter (2 divergent accesses). 2 edges/thread.
__global__ void k_fill(const int* __restrict__ row, const int* __restrict__ col) {
    int t = blockIdx.x * blockDim.x + threadIdx.x;   // N_EDGES/2 threads
    if (t >= N_EDGES / 2) return;
    int2 r2 = ((const int2*)row)[t];
    int2 c2 = ((const int2*)col)[t];
    int2 k2 = ((const int2*)g_rank)[t];

    int p0 = g_rowptr[r2.x] + k2.x;
    int p1 = g_rowptr[r2.y] + k2.y;

    g_cidx[p0] = c2.x;
    g_cidx[p1] = c2.y;
}

// K4: warp per row, HALF-WARP per edge, edge loop unrolled x2:
// two independent cidx->w->feature chains in flight per half-warp.
__global__ void k_row(float* __restrict__ h) {
    int gw = (blockIdx.x * blockDim.x + threadIdx.x) >> 5;
    int lane = threadIdx.x & 31;
    if (gw >= N_NODES) return;
    int s0 = g_rowptr[gw], s1 = g_rowptr[gw + 1];

    int half = lane >> 4;        // 0 or 1
    int hl   = lane & 15;        // lane within half-warp

    const uint4* xh = (const uint4*)g_xh;   // 16B = 8 halves per lane
    float acc[8] = {0.f, 0.f, 0.f, 0.f, 0.f, 0.f, 0.f, 0.f};
    float wsum = 0.0f;

    int i = s0 + half;
    // unrolled: edges i and i+2 (this half's consecutive edges)
    for (; i + 2 < s1; i += 4) {
        int c0 = __ldg(&g_cidx[i]);
        int c1 = __ldg(&g_cidx[i + 2]);
        float w0 = __ldg(&g_w[c0]);
        float w1 = __ldg(&g_w[c1]);
        uint4 q0 = xh[c0 * 16 + hl];
        uint4 q1 = xh[c1 * 16 + hl];
        wsum += w0 + w1;
        float2 f0 = __half22float2(*(__half2*)&q0.x);
        float2 f1 = __half22float2(*(__half2*)&q0.y);
        float2 f2 = __half22float2(*(__half2*)&q0.z);
        float2 f3 = __half22float2(*(__half2*)&q0.w);
        acc[0] += w0 * f0.x;  acc[1] += w0 * f0.y;
        acc[2] += w0 * f1.x;  acc[3] += w0 * f1.y;
        acc[4] += w0 * f2.x;  acc[5] += w0 * f2.y;
        acc[6] += w0 * f3.x;  acc[7] += w0 * f3.y;
        float2 g0 = __half22float2(*(__half2*)&q1.x);
        float2 g1 = __half22float2(*(__half2*)&q1.y);
        float2 g2 = __half22float2(*(__half2*)&q1.z);
        float2 g3 = __half22float2(*(__half2*)&q1.w);
        acc[0] += w1 * g0.x;  acc[1] += w1 * g0.y;
        acc[2] += w1 * g1.x;  acc[3] += w1 * g1.y;
        acc[4] += w1 * g2.x;  acc[5] += w1 * g2.y;
        acc[6] += w1 * g3.x;  acc[7] += w1 * g3.y;
    }
    if (i < s1) {
        int c = __ldg(&g_cidx[i]);
        float wgt = __ldg(&g_w[c]);
        wsum += wgt;
        uint4 p = xh[c * 16 + hl];
        float2 f0 = __half22float2(*(__half2*)&p.x);
        float2 f1 = __half22float2(*(__half2*)&p.y);
        float2 f2 = __half22float2(*(__half2*)&p.z);
        float2 f3 = __half22float2(*(__half2*)&p.w);
        acc[0] += wgt * f0.x;  acc[1] += wgt * f0.y;
        acc[2] += wgt * f1.x;  acc[3] += wgt * f1.y;
        acc[4] += wgt * f2.x;  acc[5] += wgt * f2.y;
        acc[6] += wgt * f3.x;  acc[7] += wgt * f3.y;
    }

    // combine the two half-warps (lane i += lane i+16)
    #pragma unroll
    for (int j = 0; j < 8; j++)
        acc[j] += __shfl_down_sync(0xffffffffu, acc[j], 16);
    wsum += __shfl_down_sync(0xffffffffu, wsum, 16);

    if (half == 0) {
        float inv = (s1 > s0) ? 1.0f / wsum : 0.0f;
        float4 o0 = make_float4(acc[0] * inv, acc[1] * inv, acc[2] * inv, acc[3] * inv);
        float4 o1 = make_float4(acc[4] * inv, acc[5] * inv, acc[6] * inv, acc[7] * inv);
        float4* dst = (float4*)(h + (size_t)gw * FEAT + hl * 8);
        dst[0] = o0;
        dst[1] = o1;
    }
}

extern "C" void kernel_launch(void* const* d_in, const int* in_sizes, int n_in,
                              void* d_out, int out_size) {
    const float* x   = (const float*)d_in[0];  // [N_NODES, FEAT]
    const float* a   = (const float*)d_in[1];  // [FEAT, 1]
    const int*   row = (const int*)d_in[2];    // [N_EDGES] int32
    const int*   col = (const int*)d_in[3];    // [N_EDGES] int32
    float* h = (float*)d_out;                  // [N_NODES, FEAT]

    int score_blocks = (N_NODES * 32 + 255) / 256;   // warp/node + thread/edge
    k_score<<<score_blocks, 256>>>(x, a, row);

    k_scanA<<<SCAN_BLOCKS, 256>>>();
    k_scanB<<<SCAN_BLOCKS, 256>>>();

    int fill_blocks = (N_EDGES / 2 + 255) / 256;     // 2 edges per thread
    k_fill<<<fill_blocks, 256>>>(row, col);

    int row_blocks = (N_NODES * 32 + 255) / 256;     // warp per row
    k_row<<<row_blocks, 256>>>(h);
}